// round 3
// baseline (speedup 1.0000x reference)
#include <cuda_runtime.h>

#define DD   6
#define KK   16
#define CIN  13
#define NL   3

typedef unsigned long long u64;

__device__ __forceinline__ u64 pk2(float lo, float hi) {
    u64 r;
    asm("mov.b64 %0, {%1, %2};" : "=l"(r) : "f"(lo), "f"(hi));
    return r;
}
__device__ __forceinline__ float2 upk2(u64 v) {
    float2 f;
    asm("mov.b64 {%0, %1}, %2;" : "=f"(f.x), "=f"(f.y) : "l"(v));
    return f;
}
__device__ __forceinline__ u64 fma2(u64 a, u64 b, u64 c) {
    u64 r;
    asm("fma.rn.f32x2 %0, %1, %2, %3;" : "=l"(r) : "l"(a), "l"(b), "l"(c));
    return r;
}
__device__ __forceinline__ u64 add2(u64 a, u64 b) {
    u64 r;
    asm("add.rn.f32x2 %0, %1, %2;" : "=l"(r) : "l"(a), "l"(b));
    return r;
}

#define W1_SZ  (NL * CIN * CIN)   // 507
#define B1_SZ  (NL * CIN)         // 39
#define W2_SZ  (NL * CIN * DD)    // 234
#define B2_SZ  (NL * DD)          // 18
#define G_SZ   (NL * DD)          // 18
#define W1P_SZ (NL * 7 * CIN)     // 273 packed duplicated rows 6..12

__global__ void __launch_bounds__(128)
atom_mp_kernel(const float* __restrict__ dist, const float* __restrict__ atom,
               const float* __restrict__ W1,   const float* __restrict__ b1,
               const float* __restrict__ W2,   const float* __restrict__ b2,
               const float* __restrict__ gw,   const float* __restrict__ gb,
               float* __restrict__ out, int P)
{
    __shared__ float sW1[W1_SZ], sb1[B1_SZ], sW2[W2_SZ], sb2[B2_SZ], sgw[G_SZ], sgb[G_SZ];
    __shared__ u64   sW1p[W1P_SZ];   // (w,w) duplicated, rows 6..12 of each layer's W1

    for (int t = threadIdx.x; t < W1_SZ; t += blockDim.x) sW1[t] = W1[t];
    for (int t = threadIdx.x; t < B1_SZ; t += blockDim.x) sb1[t] = b1[t];
    for (int t = threadIdx.x; t < W2_SZ; t += blockDim.x) sW2[t] = W2[t];
    if (threadIdx.x < B2_SZ) sb2[threadIdx.x] = b2[threadIdx.x];
    if (threadIdx.x < G_SZ)  sgw[threadIdx.x] = gw[threadIdx.x];
    if (threadIdx.x < G_SZ)  sgb[threadIdx.x] = gb[threadIdx.x];
    for (int t = threadIdx.x; t < W1P_SZ; t += blockDim.x) {
        int l = t / (7 * CIN);
        int r = t % (7 * CIN);
        int i = r / CIN;          // 0..6 -> W1 row 6+i
        int c = r % CIN;
        float w = W1[l * CIN * CIN + (6 + i) * CIN + c];
        sW1p[t] = pk2(w, w);
    }
    __syncthreads();

    int p = blockIdx.x * blockDim.x + threadIdx.x;
    if (p >= P) return;

    // ---- load this point's neighbor data (once; all 3 layers run from regs) ----
    float ar[96];
    const float4* a4 = reinterpret_cast<const float4*>(atom + (size_t)p * (KK * DD));
    #pragma unroll
    for (int t = 0; t < 24; t++) {
        float4 v = a4[t];
        ar[4*t+0] = v.x; ar[4*t+1] = v.y; ar[4*t+2] = v.z; ar[4*t+3] = v.w;
    }
    float dr[16];
    const float4* d4 = reinterpret_cast<const float4*>(dist + (size_t)p * KK);
    #pragma unroll
    for (int t = 0; t < 4; t++) {
        float4 v = d4[t];
        dr[4*t+0] = v.x; dr[4*t+1] = v.y; dr[4*t+2] = v.z; dr[4*t+3] = v.w;
    }

    // pack neighbor pairs (k=2j, 2j+1) per channel: 7 channels (6 atom + dist)
    u64 pk[8][7];
    #pragma unroll
    for (int j = 0; j < 8; j++) {
        #pragma unroll
        for (int i = 0; i < 6; i++)
            pk[j][i] = pk2(ar[12*j + i], ar[12*j + 6 + i]);
        pk[j][6] = pk2(dr[2*j], dr[2*j + 1]);
    }

    float pe[6] = {1.f, 1.f, 1.f, 1.f, 1.f, 1.f};

    #pragma unroll
    for (int l = 0; l < NL; l++) {
        const float* w1l  = sW1  + l * CIN * CIN;
        const float* b1l  = sb1  + l * CIN;
        const u64*   w1pl = sW1p + l * 7 * CIN;

        float hs[CIN];
        #pragma unroll
        for (int c = 0; c < CIN; c++) {
            // per-point shared part of feat@W1 (pe rows 0..5) + bias
            float base = b1l[c];
            #pragma unroll
            for (int q = 0; q < 6; q++)
                base = fmaf(pe[q], w1l[q * CIN + c], base);

            u64 wv[7];
            #pragma unroll
            for (int i = 0; i < 7; i++)
                wv[i] = w1pl[i * CIN + c];
            u64 basev = pk2(base, base);

            // v[j] for 8 neighbor-pairs, i-outer for ILP-8
            u64 v[8];
            #pragma unroll
            for (int j = 0; j < 8; j++) v[j] = basev;
            #pragma unroll
            for (int i = 0; i < 7; i++) {
                #pragma unroll
                for (int j = 0; j < 8; j++)
                    v[j] = fma2(pk[j][i], wv[i], v[j]);
            }

            // sum_k lrelu(v_k) = 0.6*sum(v) + 0.4*sum(|v|)
            u64 sv0 = 0ull, sv1 = 0ull, sa0 = 0ull, sa1 = 0ull;
            #pragma unroll
            for (int j = 0; j < 8; j += 2) {
                u64 a0 = v[j]     & 0x7FFFFFFF7FFFFFFFull;
                u64 a1 = v[j + 1] & 0x7FFFFFFF7FFFFFFFull;
                sv0 = add2(sv0, v[j]);
                sv1 = add2(sv1, v[j + 1]);
                sa0 = add2(sa0, a0);
                sa1 = add2(sa1, a1);
            }
            float2 sv = upk2(add2(sv0, sv1));
            float2 sa = upk2(add2(sa0, sa1));
            hs[c] = 0.6f * (sv.x + sv.y) + 0.4f * (sa.x + sa.y);
        }

        // msg = hs @ W2 + 16*b2   (k-sum pushed past W2)
        const float* w2l = sW2 + l * CIN * DD;
        float msg[6];
        #pragma unroll
        for (int d = 0; d < DD; d++) {
            float m = 16.0f * sb2[l * DD + d];
            #pragma unroll
            for (int c = 0; c < CIN; c++)
                m = fmaf(hs[c], w2l[c * DD + d], m);
            msg[d] = m;
        }

        // GroupNorm(2 groups of 3) + affine + lrelu + residual
        #pragma unroll
        for (int g = 0; g < 2; g++) {
            float x0 = msg[3*g], x1 = msg[3*g+1], x2 = msg[3*g+2];
            float mu = (x0 + x1 + x2) * (1.0f / 3.0f);
            float e0 = x0 - mu, e1 = x1 - mu, e2 = x2 - mu;
            float var = (e0*e0 + e1*e1 + e2*e2) * (1.0f / 3.0f);
            float rs = rsqrtf(var + 1e-5f);
            float ee[3] = {e0, e1, e2};
            #pragma unroll
            for (int t = 0; t < 3; t++) {
                int d = 3*g + t;
                float y = fmaf(ee[t] * rs, sgw[l * DD + d], sgb[l * DD + d]);
                pe[d] += 0.6f * y + 0.4f * fabsf(y);   // lrelu(y)
            }
        }
    }

    float2* o2 = reinterpret_cast<float2*>(out + (size_t)p * DD);
    o2[0] = make_float2(pe[0], pe[1]);
    o2[1] = make_float2(pe[2], pe[3]);
    o2[2] = make_float2(pe[4], pe[5]);
}

extern "C" void kernel_launch(void* const* d_in, const int* in_sizes, int n_in,
                              void* d_out, int out_size) {
    const float* dist = (const float*)d_in[0];
    const float* atom = (const float*)d_in[1];
    const float* W1   = (const float*)d_in[2];
    const float* b1   = (const float*)d_in[3];
    const float* W2   = (const float*)d_in[4];
    const float* b2   = (const float*)d_in[5];
    const float* gw   = (const float*)d_in[6];
    const float* gb   = (const float*)d_in[7];
    float* out = (float*)d_out;

    int P = in_sizes[0] / KK;          // B*N points (dist has K floats per point)
    int grid = (P + 127) / 128;
    atom_mp_kernel<<<grid, 128>>>(dist, atom, W1, b1, W2, b2, gw, gb, out, P);
}

// round 4
// speedup vs baseline: 1.3711x; 1.3711x over previous
#include <cuda_runtime.h>

#define DD   6
#define KK   16
#define CIN  13
#define NL   3

typedef unsigned long long u64;

__device__ __forceinline__ u64 pk2(float lo, float hi) {
    u64 r;
    asm("mov.b64 %0, {%1, %2};" : "=l"(r) : "f"(lo), "f"(hi));
    return r;
}
__device__ __forceinline__ float2 upk2(u64 v) {
    float2 f;
    asm("mov.b64 {%0, %1}, %2;" : "=f"(f.x), "=f"(f.y) : "l"(v));
    return f;
}
__device__ __forceinline__ u64 fma2(u64 a, u64 b, u64 c) {
    u64 r;
    asm("fma.rn.f32x2 %0, %1, %2, %3;" : "=l"(r) : "l"(a), "l"(b), "l"(c));
    return r;
}
__device__ __forceinline__ u64 add2(u64 a, u64 b) {
    u64 r;
    asm("add.rn.f32x2 %0, %1, %2;" : "=l"(r) : "l"(a), "l"(b));
    return r;
}

#define ABS2(x) ((x) & 0x7FFFFFFF7FFFFFFFull)

// Per-output-channel contiguous weight layouts (8-slot padded rows):
//  sBaseW[l][c][s]: s=0..5 -> W1[l][s][c] (pe rows), s=6 -> b1[l][c], s=7 pad
//  sPackW[l][c][i]: i=0..6 -> (w,w) dup of W1[l][6+i][c], i=7 pad
//  sW2r  [l][c][d]: d=0..5 -> W2[l][c][d], pad
__global__ void __launch_bounds__(128, 4)
atom_mp_kernel(const float* __restrict__ dist, const float* __restrict__ atom,
               const float* __restrict__ W1,   const float* __restrict__ b1,
               const float* __restrict__ W2,   const float* __restrict__ b2,
               const float* __restrict__ gw,   const float* __restrict__ gb,
               float* __restrict__ out, int P)
{
    __shared__ __align__(16) float sBaseW[NL * CIN * 8];
    __shared__ __align__(16) u64   sPackW[NL * CIN * 8];
    __shared__ __align__(16) float sW2r[NL * CIN * 8];
    __shared__ float sb2s[NL * DD], sgws[NL * DD], sgbs[NL * DD];

    for (int t = threadIdx.x; t < NL * CIN * 8; t += blockDim.x) {
        int l = t / (CIN * 8);
        int r = t % (CIN * 8);
        int c = r / 8;
        int s = r % 8;
        sBaseW[t] = (s < 6) ? W1[(l * CIN + s) * CIN + c]
                            : (s == 6 ? b1[l * CIN + c] : 0.f);
        float w = (s < 7) ? W1[(l * CIN + 6 + s) * CIN + c] : 0.f;
        sPackW[t] = pk2(w, w);
        sW2r[t] = (s < 6) ? W2[(l * CIN + c) * DD + s] : 0.f;
    }
    if (threadIdx.x < NL * DD) {
        sb2s[threadIdx.x] = b2[threadIdx.x];
        sgws[threadIdx.x] = gw[threadIdx.x];
        sgbs[threadIdx.x] = gb[threadIdx.x];
    }
    __syncthreads();

    int t  = blockIdx.x * blockDim.x + threadIdx.x;
    int p  = t >> 2;          // point id
    int q  = t & 3;           // lane-within-point: owns neighbors 4q..4q+3
    if (p >= P) return;
    unsigned gmask = 0xFu << (threadIdx.x & 28);  // the 4 lanes of this point

    // ---- load this lane's 4 neighbors (4*6 atom floats + 4 dist) ----
    float ar[24];
    const float4* a4 = reinterpret_cast<const float4*>(atom + (size_t)p * (KK * DD) + q * 24);
    #pragma unroll
    for (int i = 0; i < 6; i++) {
        float4 v = a4[i];
        ar[4*i+0] = v.x; ar[4*i+1] = v.y; ar[4*i+2] = v.z; ar[4*i+3] = v.w;
    }
    float4 dv = *reinterpret_cast<const float4*>(dist + (size_t)p * KK + q * 4);

    // pack neighbor pairs (local k = {0,1} and {2,3}) per channel
    u64 pkd[2][7];
    #pragma unroll
    for (int j = 0; j < 2; j++)
        #pragma unroll
        for (int i = 0; i < 6; i++)
            pkd[j][i] = pk2(ar[12*j + i], ar[12*j + 6 + i]);
    pkd[0][6] = pk2(dv.x, dv.y);
    pkd[1][6] = pk2(dv.z, dv.w);

    float pe[6] = {1.f, 1.f, 1.f, 1.f, 1.f, 1.f};

    #pragma unroll
    for (int l = 0; l < NL; l++) {
        const float* bw  = sBaseW + l * CIN * 8;
        const u64*   pw  = sPackW + l * CIN * 8;
        const float* w2  = sW2r   + l * CIN * 8;

        float msg[6] = {0.f, 0.f, 0.f, 0.f, 0.f, 0.f};

        #pragma unroll
        for (int c = 0; c < CIN; c++) {
            // base_c = b1[c] + pe . W1[0:6, c]   (b1 folded into slot 6)
            float4 bwA = *reinterpret_cast<const float4*>(bw + c * 8);
            float4 bwB = *reinterpret_cast<const float4*>(bw + c * 8 + 4);
            float base = bwB.z;
            base = fmaf(pe[0], bwA.x, base);
            base = fmaf(pe[1], bwA.y, base);
            base = fmaf(pe[2], bwA.z, base);
            base = fmaf(pe[3], bwA.w, base);
            base = fmaf(pe[4], bwB.x, base);
            base = fmaf(pe[5], bwB.y, base);
            u64 bv = pk2(base, base);

            const ulonglong2* pwc = reinterpret_cast<const ulonglong2*>(pw + c * 8);
            ulonglong2 w01 = pwc[0];
            ulonglong2 w23 = pwc[1];
            ulonglong2 w45 = pwc[2];
            ulonglong2 w6x = pwc[3];

            u64 v0 = bv, v1 = bv;
            v0 = fma2(pkd[0][0], w01.x, v0);  v1 = fma2(pkd[1][0], w01.x, v1);
            v0 = fma2(pkd[0][1], w01.y, v0);  v1 = fma2(pkd[1][1], w01.y, v1);
            v0 = fma2(pkd[0][2], w23.x, v0);  v1 = fma2(pkd[1][2], w23.x, v1);
            v0 = fma2(pkd[0][3], w23.y, v0);  v1 = fma2(pkd[1][3], w23.y, v1);
            v0 = fma2(pkd[0][4], w45.x, v0);  v1 = fma2(pkd[1][4], w45.x, v1);
            v0 = fma2(pkd[0][5], w45.y, v0);  v1 = fma2(pkd[1][5], w45.y, v1);
            v0 = fma2(pkd[0][6], w6x.x, v0);  v1 = fma2(pkd[1][6], w6x.x, v1);

            // partial sum_k lrelu(v_k) over this lane's 4 neighbors
            float2 s = upk2(add2(v0, v1));
            float2 a = upk2(add2(ABS2(v0), ABS2(v1)));
            float hc = 0.6f * (s.x + s.y) + 0.4f * (a.x + a.y);

            // fold into partial msg = hs_partial @ W2
            float4 w2A = *reinterpret_cast<const float4*>(w2 + c * 8);
            float4 w2B = *reinterpret_cast<const float4*>(w2 + c * 8 + 4);
            msg[0] = fmaf(hc, w2A.x, msg[0]);
            msg[1] = fmaf(hc, w2A.y, msg[1]);
            msg[2] = fmaf(hc, w2A.z, msg[2]);
            msg[3] = fmaf(hc, w2A.w, msg[3]);
            msg[4] = fmaf(hc, w2B.x, msg[4]);
            msg[5] = fmaf(hc, w2B.y, msg[5]);
        }

        // reduce partial msg across the 4 lanes of this point, add 16*b2
        #pragma unroll
        for (int d = 0; d < DD; d++) {
            msg[d] += __shfl_xor_sync(gmask, msg[d], 1);
            msg[d] += __shfl_xor_sync(gmask, msg[d], 2);
            msg[d] = fmaf(16.0f, sb2s[l * DD + d], msg[d]);
        }

        // GroupNorm(2 groups of 3) + affine + lrelu + residual (dup in all lanes)
        #pragma unroll
        for (int g = 0; g < 2; g++) {
            float x0 = msg[3*g], x1 = msg[3*g+1], x2 = msg[3*g+2];
            float mu = (x0 + x1 + x2) * (1.0f / 3.0f);
            float e0 = x0 - mu, e1 = x1 - mu, e2 = x2 - mu;
            float var = (e0*e0 + e1*e1 + e2*e2) * (1.0f / 3.0f);
            float rs = rsqrtf(var + 1e-5f);
            float ee[3] = {e0, e1, e2};
            #pragma unroll
            for (int u = 0; u < 3; u++) {
                int d = 3*g + u;
                float y = fmaf(ee[u] * rs, sgws[l * DD + d], sgbs[l * DD + d]);
                pe[d] += 0.6f * y + 0.4f * fabsf(y);
            }
        }
    }

    // coalesced-ish store: lane q writes pe[2q], pe[2q+1]
    float2 o;
    if (q == 0)      o = make_float2(pe[0], pe[1]);
    else if (q == 1) o = make_float2(pe[2], pe[3]);
    else             o = make_float2(pe[4], pe[5]);
    if (q < 3)
        *reinterpret_cast<float2*>(out + (size_t)p * DD + 2 * q) = o;
}

extern "C" void kernel_launch(void* const* d_in, const int* in_sizes, int n_in,
                              void* d_out, int out_size) {
    const float* dist = (const float*)d_in[0];
    const float* atom = (const float*)d_in[1];
    const float* W1   = (const float*)d_in[2];
    const float* b1   = (const float*)d_in[3];
    const float* W2   = (const float*)d_in[4];
    const float* b2   = (const float*)d_in[5];
    const float* gw   = (const float*)d_in[6];
    const float* gb   = (const float*)d_in[7];
    float* out = (float*)d_out;

    int P = in_sizes[0] / KK;                 // B*N points
    long long threads = (long long)P * 4;
    int grid = (int)((threads + 127) / 128);
    atom_mp_kernel<<<grid, 128>>>(dist, atom, W1, b1, W2, b2, gw, gb, out, P);
}

// round 5
// speedup vs baseline: 1.7869x; 1.3033x over previous
#include <cuda_runtime.h>

#define DD   6
#define KK   16
#define CIN  13
#define NL   3
#define NCP  7        // channel pairs (14 padded channels)
#define WPC  20       // u64 weights per (layer, channel-pair): bias,6 bw,7 nw,6 w2

typedef unsigned long long u64;

__device__ __forceinline__ u64 pk2(float lo, float hi) {
    u64 r;
    asm("mov.b64 %0, {%1, %2};" : "=l"(r) : "f"(lo), "f"(hi));
    return r;
}
__device__ __forceinline__ float2 upk2(u64 v) {
    float2 f;
    asm("mov.b64 {%0, %1}, %2;" : "=f"(f.x), "=f"(f.y) : "l"(v));
    return f;
}
__device__ __forceinline__ u64 fma2(u64 a, u64 b, u64 c) {
    u64 r;
    asm("fma.rn.f32x2 %0, %1, %2, %3;" : "=l"(r) : "l"(a), "l"(b), "l"(c));
    return r;
}
__device__ __forceinline__ u64 add2(u64 a, u64 b) {
    u64 r;
    asm("add.rn.f32x2 %0, %1, %2;" : "=l"(r) : "l"(a), "l"(b));
    return r;
}
__device__ __forceinline__ u64 mul2(u64 a, u64 b) {
    u64 r;
    asm("mul.rn.f32x2 %0, %1, %2;" : "=l"(r) : "l"(a), "l"(b));
    return r;
}

#define ABS2(x) ((x) & 0x7FFFFFFF7FFFFFFFull)

// sAll row per (l, cp), 20 u64 contiguous (160 B, 16B-aligned):
//   s0      : (b1[c0],  b1[c1])
//   s1..s6  : (W1[q][c0], W1[q][c1])        q = 0..5  (point-emb rows)
//   s7..s13 : (W1[6+i][c0], W1[6+i][c1])    i = 0..6  (neighbor rows)
//   s14..s19: (W2[c0][d], W2[c1][d])        d = 0..5
// c0 = 2cp, c1 = 2cp+1 (c1==13 -> zero pad)
__global__ void __launch_bounds__(128, 4)
atom_mp_kernel(const float* __restrict__ dist, const float* __restrict__ atom,
               const float* __restrict__ W1,   const float* __restrict__ b1,
               const float* __restrict__ W2,   const float* __restrict__ b2,
               const float* __restrict__ gw,   const float* __restrict__ gb,
               float* __restrict__ out, int P)
{
    __shared__ __align__(16) u64 sAll[NL * NCP * WPC];   // 420 u64 = 3360 B
    __shared__ float sb2s[NL * DD], sgws[NL * DD], sgbs[NL * DD];

    for (int t = threadIdx.x; t < NL * NCP * WPC; t += blockDim.x) {
        int l  = t / (NCP * WPC);
        int r  = t % (NCP * WPC);
        int cp = r / WPC;
        int s  = r % WPC;
        int c0 = 2 * cp, c1 = 2 * cp + 1;
        bool ok1 = (c1 < CIN);
        float lo, hi;
        if (s == 0) {
            lo = b1[l * CIN + c0];
            hi = ok1 ? b1[l * CIN + c1] : 0.f;
        } else if (s < 7) {
            int q = s - 1;
            lo = W1[(l * CIN + q) * CIN + c0];
            hi = ok1 ? W1[(l * CIN + q) * CIN + c1] : 0.f;
        } else if (s < 14) {
            int row = 6 + (s - 7);
            lo = W1[(l * CIN + row) * CIN + c0];
            hi = ok1 ? W1[(l * CIN + row) * CIN + c1] : 0.f;
        } else {
            int d = s - 14;
            lo = W2[(l * CIN + c0) * DD + d];
            hi = ok1 ? W2[(l * CIN + c1) * DD + d] : 0.f;
        }
        sAll[t] = pk2(lo, hi);
    }
    if (threadIdx.x < NL * DD) {
        sb2s[threadIdx.x] = b2[threadIdx.x];
        sgws[threadIdx.x] = gw[threadIdx.x];
        sgbs[threadIdx.x] = gb[threadIdx.x];
    }
    __syncthreads();

    int t  = blockIdx.x * blockDim.x + threadIdx.x;
    int p  = t >> 2;          // point id
    int q  = t & 3;           // lane-within-point: owns neighbors 4q..4q+3
    if (p >= P) return;
    unsigned gmask = 0xFu << (threadIdx.x & 28);

    // ---- load this lane's 4 neighbors, broadcast-pack (a,a) once ----
    float ar[24];
    const float4* a4 = reinterpret_cast<const float4*>(atom + (size_t)p * (KK * DD) + q * 24);
    #pragma unroll
    for (int i = 0; i < 6; i++) {
        float4 v = a4[i];
        ar[4*i+0] = v.x; ar[4*i+1] = v.y; ar[4*i+2] = v.z; ar[4*i+3] = v.w;
    }
    float4 dv = *reinterpret_cast<const float4*>(dist + (size_t)p * KK + q * 4);
    float dk[4] = {dv.x, dv.y, dv.z, dv.w};

    u64 nb[28];   // nb[k*7+i]: i=0..5 atom channel, i=6 dist; both halves equal
    #pragma unroll
    for (int k = 0; k < 4; k++) {
        #pragma unroll
        for (int i = 0; i < 6; i++)
            nb[k * 7 + i] = pk2(ar[k * 6 + i], ar[k * 6 + i]);
        nb[k * 7 + 6] = pk2(dk[k], dk[k]);
    }

    const u64 C06 = pk2(0.6f, 0.6f);
    const u64 C04 = pk2(0.4f, 0.4f);

    float pe[6] = {1.f, 1.f, 1.f, 1.f, 1.f, 1.f};

    #pragma unroll
    for (int l = 0; l < NL; l++) {
        const u64* WA = sAll + l * (NCP * WPC);

        u64 peb[6];
        #pragma unroll
        for (int i = 0; i < 6; i++) peb[i] = pk2(pe[i], pe[i]);

        u64 m2[6];

        #pragma unroll
        for (int cp = 0; cp < NCP; cp++) {
            const ulonglong2* w = reinterpret_cast<const ulonglong2*>(WA + cp * WPC);
            ulonglong2 L0 = w[0], L1 = w[1], L2 = w[2], L3 = w[3], L4 = w[4];
            ulonglong2 L5 = w[5], L6 = w[6], L7 = w[7], L8 = w[8], L9 = w[9];

            // base2 = (b1 + pe . W1[0:6]) for channels (c0, c1)
            u64 base2 = L0.x;
            base2 = fma2(peb[0], L0.y, base2);
            base2 = fma2(peb[1], L1.x, base2);
            base2 = fma2(peb[2], L1.y, base2);
            base2 = fma2(peb[3], L2.x, base2);
            base2 = fma2(peb[4], L2.y, base2);
            base2 = fma2(peb[5], L3.x, base2);

            // v[k] over this lane's 4 neighbors (init via first fma)
            u64 v0 = fma2(nb[0],  L3.y, base2);
            u64 v1 = fma2(nb[7],  L3.y, base2);
            u64 v2 = fma2(nb[14], L3.y, base2);
            u64 v3 = fma2(nb[21], L3.y, base2);
            v0 = fma2(nb[1],  L4.x, v0); v1 = fma2(nb[8],  L4.x, v1);
            v2 = fma2(nb[15], L4.x, v2); v3 = fma2(nb[22], L4.x, v3);
            v0 = fma2(nb[2],  L4.y, v0); v1 = fma2(nb[9],  L4.y, v1);
            v2 = fma2(nb[16], L4.y, v2); v3 = fma2(nb[23], L4.y, v3);
            v0 = fma2(nb[3],  L5.x, v0); v1 = fma2(nb[10], L5.x, v1);
            v2 = fma2(nb[17], L5.x, v2); v3 = fma2(nb[24], L5.x, v3);
            v0 = fma2(nb[4],  L5.y, v0); v1 = fma2(nb[11], L5.y, v1);
            v2 = fma2(nb[18], L5.y, v2); v3 = fma2(nb[25], L5.y, v3);
            v0 = fma2(nb[5],  L6.x, v0); v1 = fma2(nb[12], L6.x, v1);
            v2 = fma2(nb[19], L6.x, v2); v3 = fma2(nb[26], L6.x, v3);
            v0 = fma2(nb[6],  L6.y, v0); v1 = fma2(nb[13], L6.y, v1);
            v2 = fma2(nb[20], L6.y, v2); v3 = fma2(nb[27], L6.y, v3);

            // partial sum_k lrelu(v_k) = 0.6*sum v + 0.4*sum |v|, packed (c0,c1)
            u64 sv = add2(add2(v0, v1), add2(v2, v3));
            u64 sa = add2(add2(ABS2(v0), ABS2(v1)), add2(ABS2(v2), ABS2(v3)));
            u64 hc2 = fma2(sa, C04, mul2(sv, C06));

            // msg partial: packed accumulate, both channels at once
            if (cp == 0) {
                m2[0] = mul2(hc2, L7.x); m2[1] = mul2(hc2, L7.y);
                m2[2] = mul2(hc2, L8.x); m2[3] = mul2(hc2, L8.y);
                m2[4] = mul2(hc2, L9.x); m2[5] = mul2(hc2, L9.y);
            } else {
                m2[0] = fma2(hc2, L7.x, m2[0]); m2[1] = fma2(hc2, L7.y, m2[1]);
                m2[2] = fma2(hc2, L8.x, m2[2]); m2[3] = fma2(hc2, L8.y, m2[3]);
                m2[4] = fma2(hc2, L9.x, m2[4]); m2[5] = fma2(hc2, L9.y, m2[5]);
            }
        }

        // fold packed channel halves, reduce across the 4 lanes, add 16*b2
        float msg[6];
        #pragma unroll
        for (int d = 0; d < DD; d++) {
            float2 f = upk2(m2[d]);
            float m = f.x + f.y;
            m += __shfl_xor_sync(gmask, m, 1);
            m += __shfl_xor_sync(gmask, m, 2);
            msg[d] = fmaf(16.0f, sb2s[l * DD + d], m);
        }

        // GroupNorm(2 groups of 3) + affine + lrelu + residual
        #pragma unroll
        for (int g = 0; g < 2; g++) {
            float x0 = msg[3*g], x1 = msg[3*g+1], x2 = msg[3*g+2];
            float mu = (x0 + x1 + x2) * (1.0f / 3.0f);
            float e0 = x0 - mu, e1 = x1 - mu, e2 = x2 - mu;
            float var = (e0*e0 + e1*e1 + e2*e2) * (1.0f / 3.0f);
            float rs = rsqrtf(var + 1e-5f);
            float ee[3] = {e0, e1, e2};
            #pragma unroll
            for (int u = 0; u < 3; u++) {
                int d = 3*g + u;
                float y = fmaf(ee[u] * rs, sgws[l * DD + d], sgbs[l * DD + d]);
                pe[d] += 0.6f * y + 0.4f * fabsf(y);
            }
        }
    }

    // lane q writes pe[2q], pe[2q+1] (q < 3)
    float2 o;
    if (q == 0)      o = make_float2(pe[0], pe[1]);
    else if (q == 1) o = make_float2(pe[2], pe[3]);
    else             o = make_float2(pe[4], pe[5]);
    if (q < 3)
        *reinterpret_cast<float2*>(out + (size_t)p * DD + 2 * q) = o;
}

extern "C" void kernel_launch(void* const* d_in, const int* in_sizes, int n_in,
                              void* d_out, int out_size) {
    const float* dist = (const float*)d_in[0];
    const float* atom = (const float*)d_in[1];
    const float* W1   = (const float*)d_in[2];
    const float* b1   = (const float*)d_in[3];
    const float* W2   = (const float*)d_in[4];
    const float* b2   = (const float*)d_in[5];
    const float* gw   = (const float*)d_in[6];
    const float* gb   = (const float*)d_in[7];
    float* out = (float*)d_out;

    int P = in_sizes[0] / KK;                 // B*N points
    long long threads = (long long)P * 4;
    int grid = (int)((threads + 127) / 128);
    atom_mp_kernel<<<grid, 128>>>(dist, atom, W1, b1, W2, b2, gw, gb, out, P);
}

// round 6
// speedup vs baseline: 1.8569x; 1.0392x over previous
#include <cuda_runtime.h>

#define DD   6
#define KK   16
#define CIN  13
#define NL   3
#define NCP  7        // channel pairs (14 padded channels)
#define WPC  20       // u64 weights per (layer, channel-pair): bias,6 bw,7 nw,6 w2

typedef unsigned long long u64;

__device__ __forceinline__ u64 pk2(float lo, float hi) {
    u64 r;
    asm("mov.b64 %0, {%1, %2};" : "=l"(r) : "f"(lo), "f"(hi));
    return r;
}
__device__ __forceinline__ float2 upk2(u64 v) {
    float2 f;
    asm("mov.b64 {%0, %1}, %2;" : "=f"(f.x), "=f"(f.y) : "l"(v));
    return f;
}
__device__ __forceinline__ u64 fma2(u64 a, u64 b, u64 c) {
    u64 r;
    asm("fma.rn.f32x2 %0, %1, %2, %3;" : "=l"(r) : "l"(a), "l"(b), "l"(c));
    return r;
}
__device__ __forceinline__ u64 add2(u64 a, u64 b) {
    u64 r;
    asm("add.rn.f32x2 %0, %1, %2;" : "=l"(r) : "l"(a), "l"(b));
    return r;
}
__device__ __forceinline__ u64 mul2(u64 a, u64 b) {
    u64 r;
    asm("mul.rn.f32x2 %0, %1, %2;" : "=l"(r) : "l"(a), "l"(b));
    return r;
}

#define ABS2(x) ((x) & 0x7FFFFFFF7FFFFFFFull)

// sAll row per (l, cp), 20 u64 contiguous (160 B, 16B-aligned):
//   s0      : (b1[c0],  b1[c1])
//   s1..s6  : (W1[q][c0], W1[q][c1])        q = 0..5  (point-emb rows)
//   s7..s13 : (W1[6+i][c0], W1[6+i][c1])    i = 0..6  (neighbor rows)
//   s14..s19: (W2[c0][d], W2[c1][d])        d = 0..5
// c0 = 2cp, c1 = 2cp+1 (c1==13 -> zero pad)
__global__ void __launch_bounds__(128, 5)
atom_mp_kernel(const float* __restrict__ dist, const float* __restrict__ atom,
               const float* __restrict__ W1,   const float* __restrict__ b1,
               const float* __restrict__ W2,   const float* __restrict__ b2,
               const float* __restrict__ gw,   const float* __restrict__ gb,
               float* __restrict__ out, int P)
{
    __shared__ __align__(16) u64 sAll[NL * NCP * WPC];   // 420 u64 = 3360 B
    __shared__ float sb2s[NL * DD], sgws[NL * DD], sgbs[NL * DD];

    for (int t = threadIdx.x; t < NL * NCP * WPC; t += blockDim.x) {
        int l  = t / (NCP * WPC);
        int r  = t % (NCP * WPC);
        int cp = r / WPC;
        int s  = r % WPC;
        int c0 = 2 * cp, c1 = 2 * cp + 1;
        bool ok1 = (c1 < CIN);
        float lo, hi;
        if (s == 0) {
            lo = b1[l * CIN + c0];
            hi = ok1 ? b1[l * CIN + c1] : 0.f;
        } else if (s < 7) {
            int q = s - 1;
            lo = W1[(l * CIN + q) * CIN + c0];
            hi = ok1 ? W1[(l * CIN + q) * CIN + c1] : 0.f;
        } else if (s < 14) {
            int row = 6 + (s - 7);
            lo = W1[(l * CIN + row) * CIN + c0];
            hi = ok1 ? W1[(l * CIN + row) * CIN + c1] : 0.f;
        } else {
            int d = s - 14;
            lo = W2[(l * CIN + c0) * DD + d];
            hi = ok1 ? W2[(l * CIN + c1) * DD + d] : 0.f;
        }
        sAll[t] = pk2(lo, hi);
    }
    if (threadIdx.x < NL * DD) {
        sb2s[threadIdx.x] = b2[threadIdx.x];
        sgws[threadIdx.x] = gw[threadIdx.x];
        sgbs[threadIdx.x] = gb[threadIdx.x];
    }
    __syncthreads();

    int t  = blockIdx.x * blockDim.x + threadIdx.x;
    int p  = t >> 2;          // point id
    int q  = t & 3;           // lane-within-point: owns neighbors 4q..4q+3
    if (p >= P) return;
    unsigned gmask = 0xFu << (threadIdx.x & 28);

    // ---- load this lane's 4 neighbors, broadcast-pack (a,a) once ----
    float ar[24];
    const float4* a4 = reinterpret_cast<const float4*>(atom + (size_t)p * (KK * DD) + q * 24);
    #pragma unroll
    for (int i = 0; i < 6; i++) {
        float4 v = a4[i];
        ar[4*i+0] = v.x; ar[4*i+1] = v.y; ar[4*i+2] = v.z; ar[4*i+3] = v.w;
    }
    float4 dv = *reinterpret_cast<const float4*>(dist + (size_t)p * KK + q * 4);
    float dk[4] = {dv.x, dv.y, dv.z, dv.w};

    u64 nb[28];   // nb[k*7+i]: i=0..5 atom channel, i=6 dist; both halves equal
    #pragma unroll
    for (int k = 0; k < 4; k++) {
        #pragma unroll
        for (int i = 0; i < 6; i++)
            nb[k * 7 + i] = pk2(ar[k * 6 + i], ar[k * 6 + i]);
        nb[k * 7 + 6] = pk2(dk[k], dk[k]);
    }

    const u64 C06 = pk2(0.6f, 0.6f);
    const u64 C04 = pk2(0.4f, 0.4f);

    float pe[6] = {1.f, 1.f, 1.f, 1.f, 1.f, 1.f};

    #pragma unroll
    for (int l = 0; l < NL; l++) {
        const u64* WA = sAll + l * (NCP * WPC);

        u64 peb[6];
        #pragma unroll
        for (int i = 0; i < 6; i++) peb[i] = pk2(pe[i], pe[i]);

        u64 m2[6];

        #pragma unroll
        for (int cp = 0; cp < NCP; cp++) {
            const ulonglong2* w = reinterpret_cast<const ulonglong2*>(WA + cp * WPC);
            // group 1: bias + pe rows + neighbor rows (used immediately)
            ulonglong2 L0 = w[0], L1 = w[1], L2 = w[2], L3 = w[3], L4 = w[4];
            ulonglong2 L5 = w[5], L6 = w[6];

            // base2 = (b1 + pe . W1[0:6]) for channels (c0, c1) — 2-tree to cut dep chain
            u64 ba = fma2(peb[0], L0.y, L0.x);
            u64 bb = mul2(peb[1], L1.x);
            ba = fma2(peb[2], L1.y, ba);
            bb = fma2(peb[3], L2.x, bb);
            ba = fma2(peb[4], L2.y, ba);
            bb = fma2(peb[5], L3.x, bb);
            u64 base2 = add2(ba, bb);

            // v[k] over this lane's 4 neighbors (init via first fma)
            u64 v0 = fma2(nb[0],  L3.y, base2);
            u64 v1 = fma2(nb[7],  L3.y, base2);
            u64 v2 = fma2(nb[14], L3.y, base2);
            u64 v3 = fma2(nb[21], L3.y, base2);
            v0 = fma2(nb[1],  L4.x, v0); v1 = fma2(nb[8],  L4.x, v1);
            v2 = fma2(nb[15], L4.x, v2); v3 = fma2(nb[22], L4.x, v3);
            v0 = fma2(nb[2],  L4.y, v0); v1 = fma2(nb[9],  L4.y, v1);
            v2 = fma2(nb[16], L4.y, v2); v3 = fma2(nb[23], L4.y, v3);
            v0 = fma2(nb[3],  L5.x, v0); v1 = fma2(nb[10], L5.x, v1);
            v2 = fma2(nb[17], L5.x, v2); v3 = fma2(nb[24], L5.x, v3);
            v0 = fma2(nb[4],  L5.y, v0); v1 = fma2(nb[11], L5.y, v1);
            v2 = fma2(nb[18], L5.y, v2); v3 = fma2(nb[25], L5.y, v3);
            v0 = fma2(nb[5],  L6.x, v0); v1 = fma2(nb[12], L6.x, v1);
            v2 = fma2(nb[19], L6.x, v2); v3 = fma2(nb[26], L6.x, v3);
            v0 = fma2(nb[6],  L6.y, v0); v1 = fma2(nb[13], L6.y, v1);
            v2 = fma2(nb[20], L6.y, v2); v3 = fma2(nb[27], L6.y, v3);

            // partial sum_k lrelu(v_k) = 0.6*sum v + 0.4*sum |v|, packed (c0,c1)
            u64 sv = add2(add2(v0, v1), add2(v2, v3));
            u64 sa = add2(add2(ABS2(v0), ABS2(v1)), add2(ABS2(v2), ABS2(v3)));
            u64 hc2 = fma2(sa, C04, mul2(sv, C06));

            // group 2: W2 rows, loaded at use site (short live range)
            ulonglong2 L7 = w[7], L8 = w[8], L9 = w[9];

            // msg partial: packed accumulate, both channels at once
            if (cp == 0) {
                m2[0] = mul2(hc2, L7.x); m2[1] = mul2(hc2, L7.y);
                m2[2] = mul2(hc2, L8.x); m2[3] = mul2(hc2, L8.y);
                m2[4] = mul2(hc2, L9.x); m2[5] = mul2(hc2, L9.y);
            } else {
                m2[0] = fma2(hc2, L7.x, m2[0]); m2[1] = fma2(hc2, L7.y, m2[1]);
                m2[2] = fma2(hc2, L8.x, m2[2]); m2[3] = fma2(hc2, L8.y, m2[3]);
                m2[4] = fma2(hc2, L9.x, m2[4]); m2[5] = fma2(hc2, L9.y, m2[5]);
            }
        }

        // fold packed channel halves, reduce across the 4 lanes, add 16*b2
        float msg[6];
        #pragma unroll
        for (int d = 0; d < DD; d++) {
            float2 f = upk2(m2[d]);
            float m = f.x + f.y;
            m += __shfl_xor_sync(gmask, m, 1);
            m += __shfl_xor_sync(gmask, m, 2);
            msg[d] = fmaf(16.0f, sb2s[l * DD + d], m);
        }

        // GroupNorm(2 groups of 3) + affine + lrelu + residual
        #pragma unroll
        for (int g = 0; g < 2; g++) {
            float x0 = msg[3*g], x1 = msg[3*g+1], x2 = msg[3*g+2];
            float mu = (x0 + x1 + x2) * (1.0f / 3.0f);
            float e0 = x0 - mu, e1 = x1 - mu, e2 = x2 - mu;
            float var = (e0*e0 + e1*e1 + e2*e2) * (1.0f / 3.0f);
            float rs = rsqrtf(var + 1e-5f);
            float ee[3] = {e0, e1, e2};
            #pragma unroll
            for (int u = 0; u < 3; u++) {
                int d = 3*g + u;
                float y = fmaf(ee[u] * rs, sgws[l * DD + d], sgbs[l * DD + d]);
                pe[d] += 0.6f * y + 0.4f * fabsf(y);
            }
        }
    }

    // lane q writes pe[2q], pe[2q+1] (q < 3)
    float2 o;
    if (q == 0)      o = make_float2(pe[0], pe[1]);
    else if (q == 1) o = make_float2(pe[2], pe[3]);
    else             o = make_float2(pe[4], pe[5]);
    if (q < 3)
        *reinterpret_cast<float2*>(out + (size_t)p * DD + 2 * q) = o;
}

extern "C" void kernel_launch(void* const* d_in, const int* in_sizes, int n_in,
                              void* d_out, int out_size) {
    const float* dist = (const float*)d_in[0];
    const float* atom = (const float*)d_in[1];
    const float* W1   = (const float*)d_in[2];
    const float* b1   = (const float*)d_in[3];
    const float* W2   = (const float*)d_in[4];
    const float* b2   = (const float*)d_in[5];
    const float* gw   = (const float*)d_in[6];
    const float* gb   = (const float*)d_in[7];
    float* out = (float*)d_out;

    int P = in_sizes[0] / KK;                 // B*N points
    long long threads = (long long)P * 4;
    int grid = (int)((threads + 127) / 128);
    atom_mp_kernel<<<grid, 128>>>(dist, atom, W1, b1, W2, b2, gw, gb, out, P);
}

// round 7
// speedup vs baseline: 2.3397x; 1.2600x over previous
#include <cuda_runtime.h>

#define DD   6
#define KK   16
#define CIN  13
#define NL   3
#define NCP  7        // channel pairs (14 padded channels)
#define WPC  20       // u64 weights per (layer, channel-pair): bias,6 bw,7 nw,6 w2

typedef unsigned long long u64;

__device__ __forceinline__ u64 pk2(float lo, float hi) {
    u64 r;
    asm("mov.b64 %0, {%1, %2};" : "=l"(r) : "f"(lo), "f"(hi));
    return r;
}
__device__ __forceinline__ float2 upk2(u64 v) {
    float2 f;
    asm("mov.b64 {%0, %1}, %2;" : "=f"(f.x), "=f"(f.y) : "l"(v));
    return f;
}
__device__ __forceinline__ u64 fma2(u64 a, u64 b, u64 c) {
    u64 r;
    asm("fma.rn.f32x2 %0, %1, %2, %3;" : "=l"(r) : "l"(a), "l"(b), "l"(c));
    return r;
}
__device__ __forceinline__ u64 add2(u64 a, u64 b) {
    u64 r;
    asm("add.rn.f32x2 %0, %1, %2;" : "=l"(r) : "l"(a), "l"(b));
    return r;
}
__device__ __forceinline__ u64 mul2(u64 a, u64 b) {
    u64 r;
    asm("mul.rn.f32x2 %0, %1, %2;" : "=l"(r) : "l"(a), "l"(b));
    return r;
}

#define ABS2(x) ((x) & 0x7FFFFFFF7FFFFFFFull)

// Packed weight row per (l, cp), 20 u64 contiguous:
//   s0      : (b1[c0],  b1[c1])
//   s1..s6  : (W1[q][c0], W1[q][c1])        q = 0..5  (point-emb rows)
//   s7..s13 : (W1[6+i][c0], W1[6+i][c1])    i = 0..6  (neighbor rows)
//   s14..s19: (W2[c0][d], W2[c1][d])        d = 0..5
// c0 = 2cp, c1 = 2cp+1 (c1==13 -> zero pad)
__device__ __align__(16) u64 gStage[NL * NCP * WPC];
__device__ float gStageMisc[3 * NL * DD];

__constant__ __align__(16) u64 cPack[NL * NCP * WPC];
__constant__ float cMisc[3 * NL * DD];   // [0..17]=b2, [18..35]=gw, [36..53]=gb

__global__ void pack_weights_kernel(const float* __restrict__ W1, const float* __restrict__ b1,
                                    const float* __restrict__ W2, const float* __restrict__ b2,
                                    const float* __restrict__ gw, const float* __restrict__ gb)
{
    for (int t = threadIdx.x; t < NL * NCP * WPC; t += blockDim.x) {
        int l  = t / (NCP * WPC);
        int r  = t % (NCP * WPC);
        int cp = r / WPC;
        int s  = r % WPC;
        int c0 = 2 * cp, c1 = 2 * cp + 1;
        bool ok1 = (c1 < CIN);
        float lo, hi;
        if (s == 0) {
            lo = b1[l * CIN + c0];
            hi = ok1 ? b1[l * CIN + c1] : 0.f;
        } else if (s < 7) {
            int q = s - 1;
            lo = W1[(l * CIN + q) * CIN + c0];
            hi = ok1 ? W1[(l * CIN + q) * CIN + c1] : 0.f;
        } else if (s < 14) {
            int row = 6 + (s - 7);
            lo = W1[(l * CIN + row) * CIN + c0];
            hi = ok1 ? W1[(l * CIN + row) * CIN + c1] : 0.f;
        } else {
            int d = s - 14;
            lo = W2[(l * CIN + c0) * DD + d];
            hi = ok1 ? W2[(l * CIN + c1) * DD + d] : 0.f;
        }
        gStage[t] = pk2(lo, hi);
    }
    if (threadIdx.x < NL * DD) {
        gStageMisc[threadIdx.x]               = b2[threadIdx.x];
        gStageMisc[NL * DD + threadIdx.x]     = gw[threadIdx.x];
        gStageMisc[2 * NL * DD + threadIdx.x] = gb[threadIdx.x];
    }
}

__global__ void __launch_bounds__(128, 6)
atom_mp_kernel(const float* __restrict__ dist, const float* __restrict__ atom,
               float* __restrict__ out, int P)
{
    int t  = blockIdx.x * blockDim.x + threadIdx.x;
    int p  = t >> 2;          // point id
    int q  = t & 3;           // lane-within-point: owns neighbors 4q..4q+3
    if (p >= P) return;
    unsigned gmask = 0xFu << (threadIdx.x & 28);

    // ---- load this lane's 4 neighbors, broadcast-pack (a,a) once ----
    float ar[24];
    const float4* a4 = reinterpret_cast<const float4*>(atom + (size_t)p * (KK * DD) + q * 24);
    #pragma unroll
    for (int i = 0; i < 6; i++) {
        float4 v = a4[i];
        ar[4*i+0] = v.x; ar[4*i+1] = v.y; ar[4*i+2] = v.z; ar[4*i+3] = v.w;
    }
    float4 dv = *reinterpret_cast<const float4*>(dist + (size_t)p * KK + q * 4);
    float dk[4] = {dv.x, dv.y, dv.z, dv.w};

    u64 nb[28];   // nb[k*7+i]: i=0..5 atom channel, i=6 dist; both halves equal
    #pragma unroll
    for (int k = 0; k < 4; k++) {
        #pragma unroll
        for (int i = 0; i < 6; i++)
            nb[k * 7 + i] = pk2(ar[k * 6 + i], ar[k * 6 + i]);
        nb[k * 7 + 6] = pk2(dk[k], dk[k]);
    }

    const u64 C06 = pk2(0.6f, 0.6f);
    const u64 C04 = pk2(0.4f, 0.4f);

    float pe[6] = {1.f, 1.f, 1.f, 1.f, 1.f, 1.f};

    #pragma unroll
    for (int l = 0; l < NL; l++) {
        u64 peb[6];
        #pragma unroll
        for (int i = 0; i < 6; i++) peb[i] = pk2(pe[i], pe[i]);

        u64 m2[6];

        #pragma unroll
        for (int cp = 0; cp < NCP; cp++) {
            const int o = (l * NCP + cp) * WPC;   // compile-time after unroll -> LDCU

            // base2 = (b1 + pe . W1[0:6]) for channels (c0, c1) — 2-tree dep chain
            u64 ba = fma2(peb[0], cPack[o + 1], cPack[o + 0]);
            u64 bb = mul2(peb[1], cPack[o + 2]);
            ba = fma2(peb[2], cPack[o + 3], ba);
            bb = fma2(peb[3], cPack[o + 4], bb);
            ba = fma2(peb[4], cPack[o + 5], ba);
            bb = fma2(peb[5], cPack[o + 6], bb);
            u64 base2 = add2(ba, bb);

            // v[k] over this lane's 4 neighbors (init via first fma)
            u64 w;
            w = cPack[o + 7];
            u64 v0 = fma2(nb[0],  w, base2);
            u64 v1 = fma2(nb[7],  w, base2);
            u64 v2 = fma2(nb[14], w, base2);
            u64 v3 = fma2(nb[21], w, base2);
            w = cPack[o + 8];
            v0 = fma2(nb[1],  w, v0); v1 = fma2(nb[8],  w, v1);
            v2 = fma2(nb[15], w, v2); v3 = fma2(nb[22], w, v3);
            w = cPack[o + 9];
            v0 = fma2(nb[2],  w, v0); v1 = fma2(nb[9],  w, v1);
            v2 = fma2(nb[16], w, v2); v3 = fma2(nb[23], w, v3);
            w = cPack[o + 10];
            v0 = fma2(nb[3],  w, v0); v1 = fma2(nb[10], w, v1);
            v2 = fma2(nb[17], w, v2); v3 = fma2(nb[24], w, v3);
            w = cPack[o + 11];
            v0 = fma2(nb[4],  w, v0); v1 = fma2(nb[11], w, v1);
            v2 = fma2(nb[18], w, v2); v3 = fma2(nb[25], w, v3);
            w = cPack[o + 12];
            v0 = fma2(nb[5],  w, v0); v1 = fma2(nb[12], w, v1);
            v2 = fma2(nb[19], w, v2); v3 = fma2(nb[26], w, v3);
            w = cPack[o + 13];
            v0 = fma2(nb[6],  w, v0); v1 = fma2(nb[13], w, v1);
            v2 = fma2(nb[20], w, v2); v3 = fma2(nb[27], w, v3);

            // partial sum_k lrelu(v_k) = 0.6*sum v + 0.4*sum |v|, packed (c0,c1)
            u64 sv = add2(add2(v0, v1), add2(v2, v3));
            u64 sa = add2(add2(ABS2(v0), ABS2(v1)), add2(ABS2(v2), ABS2(v3)));
            u64 hc2 = fma2(sa, C04, mul2(sv, C06));

            // msg partial: packed accumulate, both channels at once
            if (cp == 0) {
                m2[0] = mul2(hc2, cPack[o + 14]); m2[1] = mul2(hc2, cPack[o + 15]);
                m2[2] = mul2(hc2, cPack[o + 16]); m2[3] = mul2(hc2, cPack[o + 17]);
                m2[4] = mul2(hc2, cPack[o + 18]); m2[5] = mul2(hc2, cPack[o + 19]);
            } else {
                m2[0] = fma2(hc2, cPack[o + 14], m2[0]); m2[1] = fma2(hc2, cPack[o + 15], m2[1]);
                m2[2] = fma2(hc2, cPack[o + 16], m2[2]); m2[3] = fma2(hc2, cPack[o + 17], m2[3]);
                m2[4] = fma2(hc2, cPack[o + 18], m2[4]); m2[5] = fma2(hc2, cPack[o + 19], m2[5]);
            }
        }

        // fold packed channel halves, reduce across the 4 lanes, add 16*b2
        float msg[6];
        #pragma unroll
        for (int d = 0; d < DD; d++) {
            float2 f = upk2(m2[d]);
            float m = f.x + f.y;
            m += __shfl_xor_sync(gmask, m, 1);
            m += __shfl_xor_sync(gmask, m, 2);
            msg[d] = fmaf(16.0f, cMisc[l * DD + d], m);
        }

        // GroupNorm(2 groups of 3) + affine + lrelu + residual
        #pragma unroll
        for (int g = 0; g < 2; g++) {
            float x0 = msg[3*g], x1 = msg[3*g+1], x2 = msg[3*g+2];
            float mu = (x0 + x1 + x2) * (1.0f / 3.0f);
            float e0 = x0 - mu, e1 = x1 - mu, e2 = x2 - mu;
            float var = (e0*e0 + e1*e1 + e2*e2) * (1.0f / 3.0f);
            float rs = rsqrtf(var + 1e-5f);
            float ee[3] = {e0, e1, e2};
            #pragma unroll
            for (int u = 0; u < 3; u++) {
                int d = 3*g + u;
                float y = fmaf(ee[u] * rs, cMisc[NL * DD + l * DD + d],
                                           cMisc[2 * NL * DD + l * DD + d]);
                pe[d] += 0.6f * y + 0.4f * fabsf(y);
            }
        }
    }

    // lane q writes pe[2q], pe[2q+1] (q < 3)
    float2 o;
    if (q == 0)      o = make_float2(pe[0], pe[1]);
    else if (q == 1) o = make_float2(pe[2], pe[3]);
    else             o = make_float2(pe[4], pe[5]);
    if (q < 3)
        *reinterpret_cast<float2*>(out + (size_t)p * DD + 2 * q) = o;
}

extern "C" void kernel_launch(void* const* d_in, const int* in_sizes, int n_in,
                              void* d_out, int out_size) {
    const float* dist = (const float*)d_in[0];
    const float* atom = (const float*)d_in[1];
    const float* W1   = (const float*)d_in[2];
    const float* b1   = (const float*)d_in[3];
    const float* W2   = (const float*)d_in[4];
    const float* b2   = (const float*)d_in[5];
    const float* gw   = (const float*)d_in[6];
    const float* gb   = (const float*)d_in[7];
    float* out = (float*)d_out;

    // 1) pack weights into staging (device global)
    pack_weights_kernel<<<1, 128>>>(W1, b1, W2, b2, gw, gb);

    // 2) DtoD copy staging -> __constant__ (graph-capturable memcpy nodes)
    void *dstP = nullptr, *srcP = nullptr, *dstM = nullptr, *srcM = nullptr;
    cudaGetSymbolAddress(&dstP, cPack);
    cudaGetSymbolAddress(&srcP, gStage);
    cudaGetSymbolAddress(&dstM, cMisc);
    cudaGetSymbolAddress(&srcM, gStageMisc);
    cudaMemcpyAsync(dstP, srcP, sizeof(u64) * NL * NCP * WPC, cudaMemcpyDeviceToDevice);
    cudaMemcpyAsync(dstM, srcM, sizeof(float) * 3 * NL * DD, cudaMemcpyDeviceToDevice);

    // 3) main kernel
    int P = in_sizes[0] / KK;                 // B*N points
    long long threads = (long long)P * 4;
    int grid = (int)((threads + 127) / 128);
    atom_mp_kernel<<<grid, 128>>>(dist, atom, out, P);
}